// round 1
// baseline (speedup 1.0000x reference)
#include <cuda_runtime.h>
#include <cuda_bf16.h>
#include <math.h>

// ---------------- problem constants ----------------
#define TOK     2048          // tokens (B*S)
#define HDIM    1024          // hidden
#define FDIM    512           // expert intermediate
#define F2DIM   1024          // shared intermediate (2F)
#define NEXP    64            // experts
#define TOPK    8
#define NGRP    8
#define TGRP    4
#define CAPE    1024          // per-expert capacity
#define SKTOT   (TOK*TOPK)    // 16384 slots
#define SCALE   2.5f

// ---------------- device scratch (static, no runtime alloc) ----------------
__device__ float g_hbuf[SKTOT * FDIM];        // expert SwiGLU activations (compact rows)
__device__ float g_hs[TOK * F2DIM];           // shared-expert SwiGLU activations
__device__ int   g_topk_idx[SKTOT];
__device__ float g_topk_w[SKTOT];
__device__ int   g_counts[NEXP];
__device__ int   g_fill[NEXP];
__device__ int   g_offsets[NEXP];
__device__ int   g_ecount[NEXP];              // min(count, CAP)
__device__ int   g_row_token[SKTOT];
__device__ float g_row_weight[SKTOT];

// ---------------- init: zero small control arrays ----------------
__global__ void init_kernel() {
    int i = threadIdx.x;
    if (i < NEXP) { g_counts[i] = 0; g_fill[i] = 0; }
}

// ---------------- routing: logits -> sigmoid -> group-limited top-k ----------------
__global__ __launch_bounds__(256) void route_kernel(const float* __restrict__ x,
                                                    const float* __restrict__ gw,
                                                    const float* __restrict__ eb) {
    const int t = blockIdx.x;
    __shared__ float xs[HDIM];
    __shared__ float sc[NEXP];    // sigmoid scores
    __shared__ float sfc[NEXP];   // scores + bias
    const int tid = threadIdx.x;
    const float* xr = x + (size_t)t * HDIM;
    #pragma unroll
    for (int i = 0; i < HDIM / 256; i++) xs[tid + i * 256] = xr[tid + i * 256];
    __syncthreads();

    const int warp = tid >> 5, lane = tid & 31;
    for (int q = 0; q < NEXP / 8; q++) {
        const int e = warp * 8 + q;
        const float* gwe = gw + (size_t)e * HDIM;
        float s = 0.f;
        #pragma unroll
        for (int i = 0; i < HDIM / 32; i++)
            s = fmaf(xs[i * 32 + lane], gwe[i * 32 + lane], s);
        #pragma unroll
        for (int off = 16; off; off >>= 1) s += __shfl_down_sync(0xffffffffu, s, off);
        if (lane == 0) {
            float sig = 1.f / (1.f + expf(-s));
            sc[e] = sig;
            sfc[e] = sig + eb[e];
        }
    }
    __syncthreads();

    if (tid == 0) {
        // group scores = sum of top-2 sfc within each group of 8
        float gsc[NGRP];
        #pragma unroll
        for (int g = 0; g < NGRP; g++) {
            float m1 = -1e30f, m2 = -1e30f;
            #pragma unroll
            for (int j = 0; j < NEXP / NGRP; j++) {
                float v = sfc[g * (NEXP / NGRP) + j];
                if (v > m1) { m2 = m1; m1 = v; } else if (v > m2) { m2 = v; }
            }
            gsc[g] = m1 + m2;
        }
        // pick TGRP groups (ties -> lowest index, matching jax top_k)
        bool gsel[NGRP];
        #pragma unroll
        for (int g = 0; g < NGRP; g++) gsel[g] = false;
        for (int it = 0; it < TGRP; it++) {
            float best = -1e30f; int bi = 0;
            #pragma unroll
            for (int g = 0; g < NGRP; g++)
                if (!gsel[g] && gsc[g] > best) { best = gsc[g]; bi = g; }
            gsel[bi] = true;
        }
        // masked values, top-K (ties -> lowest index)
        float tmp[NEXP];
        #pragma unroll
        for (int e = 0; e < NEXP; e++)
            tmp[e] = gsel[e / (NEXP / NGRP)] ? sfc[e] : 0.0f;
        int   idx[TOPK];
        float wv[TOPK];
        float wsum = 0.f;
        for (int k = 0; k < TOPK; k++) {
            float best = -1e30f; int bi = 0;
            #pragma unroll
            for (int e = 0; e < NEXP; e++)
                if (tmp[e] > best) { best = tmp[e]; bi = e; }
            idx[k] = bi; tmp[bi] = -1e30f;
            wv[k] = sc[bi]; wsum += wv[k];
        }
        float inv = SCALE / (wsum + 1e-20f);
        for (int k = 0; k < TOPK; k++) {
            g_topk_idx[t * TOPK + k] = idx[k];
            g_topk_w[t * TOPK + k] = wv[k] * inv;
            atomicAdd(&g_counts[idx[k]], 1);
        }
    }
}

// ---------------- scan: exclusive prefix of clamped counts ----------------
__global__ void scan_kernel() {
    if (threadIdx.x == 0) {
        int run = 0;
        for (int e = 0; e < NEXP; e++) {
            int c = g_counts[e];
            int cc = c < CAPE ? c : CAPE;
            g_offsets[e] = run;
            g_ecount[e] = cc;
            run += cc;
        }
    }
}

// ---------------- assign compact rows ----------------
__global__ void assign_kernel() {
    int s = blockIdx.x * blockDim.x + threadIdx.x;
    if (s >= SKTOT) return;
    int e = g_topk_idx[s];
    int p = atomicAdd(&g_fill[e], 1);
    if (p < CAPE) {
        int r = g_offsets[e] + p;
        g_row_token[r] = s / TOPK;
        g_row_weight[r] = g_topk_w[s];
    }
}

// ---------------- tiled GEMM config ----------------
#define BM 64
#define BN 64
#define BK 16

// GEMM1 (expert, fused gate/up + SwiGLU):
// Hbuf[r, n] = silu(sum_k x[tok(r),k]*w1[e,n,k]) * (sum_k x[tok(r),k]*w3[e,n,k])
__global__ __launch_bounds__(256) void expert_gemm1(const float* __restrict__ x,
                                                    const float* __restrict__ w1,
                                                    const float* __restrict__ w3) {
    const int e = blockIdx.z;
    const int me = g_ecount[e];
    const int m0 = blockIdx.y * BM;
    if (m0 >= me) return;
    const int n0 = blockIdx.x * BN;
    const int roff = g_offsets[e];

    __shared__ float As[BK][BM];
    __shared__ float B1s[BK][BN];
    __shared__ float B3s[BK][BN];
    __shared__ int tok[BM];

    const int tid = threadIdx.x;
    if (tid < BM) {
        int m = m0 + tid;
        tok[tid] = (m < me) ? g_row_token[roff + m] : -1;
    }
    __syncthreads();

    const int lr = tid >> 2;            // 0..63 row within tile
    const int lk = (tid & 3) * 4;       // 0,4,8,12
    const float* w1p = w1 + (size_t)e * FDIM * HDIM + (size_t)(n0 + lr) * HDIM;
    const float* w3p = w3 + (size_t)e * FDIM * HDIM + (size_t)(n0 + lr) * HDIM;
    const int tkn = tok[lr];
    const float* xp = (tkn >= 0) ? (x + (size_t)tkn * HDIM) : x;  // safe dummy
    const bool avalid = (tkn >= 0);

    const int tx = tid & 15, ty = tid >> 4;
    float accG[4][4] = {{0}}, accU[4][4] = {{0}};

    for (int k0 = 0; k0 < HDIM; k0 += BK) {
        float4 av = make_float4(0.f, 0.f, 0.f, 0.f);
        if (avalid) av = *(const float4*)(xp + k0 + lk);
        As[lk + 0][lr] = av.x; As[lk + 1][lr] = av.y;
        As[lk + 2][lr] = av.z; As[lk + 3][lr] = av.w;
        float4 b1 = *(const float4*)(w1p + k0 + lk);
        B1s[lk + 0][lr] = b1.x; B1s[lk + 1][lr] = b1.y;
        B1s[lk + 2][lr] = b1.z; B1s[lk + 3][lr] = b1.w;
        float4 b3 = *(const float4*)(w3p + k0 + lk);
        B3s[lk + 0][lr] = b3.x; B3s[lk + 1][lr] = b3.y;
        B3s[lk + 2][lr] = b3.z; B3s[lk + 3][lr] = b3.w;
        __syncthreads();
        #pragma unroll
        for (int kk = 0; kk < BK; kk++) {
            float4 a  = *(const float4*)&As[kk][ty * 4];
            float4 b1v = *(const float4*)&B1s[kk][tx * 4];
            float4 b3v = *(const float4*)&B3s[kk][tx * 4];
            float aa[4] = {a.x, a.y, a.z, a.w};
            float g4[4] = {b1v.x, b1v.y, b1v.z, b1v.w};
            float u4[4] = {b3v.x, b3v.y, b3v.z, b3v.w};
            #pragma unroll
            for (int i = 0; i < 4; i++) {
                #pragma unroll
                for (int j = 0; j < 4; j++) {
                    accG[i][j] = fmaf(aa[i], g4[j], accG[i][j]);
                    accU[i][j] = fmaf(aa[i], u4[j], accU[i][j]);
                }
            }
        }
        __syncthreads();
    }
    #pragma unroll
    for (int i = 0; i < 4; i++) {
        int m = m0 + ty * 4 + i;
        if (m < me) {
            int row = roff + m;
            float4 hv;
            float* o = (float*)&hv;
            #pragma unroll
            for (int j = 0; j < 4; j++) {
                float g = accG[i][j], u = accU[i][j];
                o[j] = g / (1.f + expf(-g)) * u;
            }
            *(float4*)(g_hbuf + (size_t)row * FDIM + n0 + tx * 4) = hv;
        }
    }
}

// GEMM2 (expert down-proj + weighted scatter-add):
// out[tok(r), n] += weight(r) * sum_k Hbuf[r,k]*w2[e,n,k]
__global__ __launch_bounds__(256) void expert_gemm2(const float* __restrict__ w2,
                                                    float* __restrict__ out) {
    const int e = blockIdx.z;
    const int me = g_ecount[e];
    const int m0 = blockIdx.y * BM;
    if (m0 >= me) return;
    const int n0 = blockIdx.x * BN;
    const int roff = g_offsets[e];

    __shared__ float As[BK][BM];
    __shared__ float Bs[BK][BN];
    __shared__ int tok[BM];
    __shared__ float wrow[BM];

    const int tid = threadIdx.x;
    if (tid < BM) {
        int m = m0 + tid;
        bool v = (m < me);
        tok[tid] = v ? g_row_token[roff + m] : -1;
        wrow[tid] = v ? g_row_weight[roff + m] : 0.f;
    }
    __syncthreads();

    const int lr = tid >> 2;
    const int lk = (tid & 3) * 4;
    const float* w2p = w2 + (size_t)e * HDIM * FDIM + (size_t)(n0 + lr) * FDIM;
    const bool avalid = (m0 + lr < me);
    const float* ap = g_hbuf + (size_t)(roff + m0 + lr) * FDIM;

    const int tx = tid & 15, ty = tid >> 4;
    float acc[4][4] = {{0}};

    for (int k0 = 0; k0 < FDIM; k0 += BK) {
        float4 av = make_float4(0.f, 0.f, 0.f, 0.f);
        if (avalid) av = *(const float4*)(ap + k0 + lk);
        As[lk + 0][lr] = av.x; As[lk + 1][lr] = av.y;
        As[lk + 2][lr] = av.z; As[lk + 3][lr] = av.w;
        float4 bv = *(const float4*)(w2p + k0 + lk);
        Bs[lk + 0][lr] = bv.x; Bs[lk + 1][lr] = bv.y;
        Bs[lk + 2][lr] = bv.z; Bs[lk + 3][lr] = bv.w;
        __syncthreads();
        #pragma unroll
        for (int kk = 0; kk < BK; kk++) {
            float4 a = *(const float4*)&As[kk][ty * 4];
            float4 b = *(const float4*)&Bs[kk][tx * 4];
            float aa[4] = {a.x, a.y, a.z, a.w};
            float bb[4] = {b.x, b.y, b.z, b.w};
            #pragma unroll
            for (int i = 0; i < 4; i++)
                #pragma unroll
                for (int j = 0; j < 4; j++)
                    acc[i][j] = fmaf(aa[i], bb[j], acc[i][j]);
        }
        __syncthreads();
    }
    #pragma unroll
    for (int i = 0; i < 4; i++) {
        int m = m0 + ty * 4 + i;
        if (m < me) {
            int t = tok[ty * 4 + i];
            float w = wrow[ty * 4 + i];
            float* op = out + (size_t)t * HDIM + n0 + tx * 4;
            #pragma unroll
            for (int j = 0; j < 4; j++) atomicAdd(op + j, acc[i][j] * w);
        }
    }
}

// Shared expert GEMM1: g_hs[t,n] = silu(x@sg^T)*(x@su^T)   [TOK x F2DIM]
__global__ __launch_bounds__(256) void shared_gemm1(const float* __restrict__ x,
                                                    const float* __restrict__ sg,
                                                    const float* __restrict__ su) {
    const int m0 = blockIdx.y * BM;
    const int n0 = blockIdx.x * BN;
    __shared__ float As[BK][BM];
    __shared__ float B1s[BK][BN];
    __shared__ float B3s[BK][BN];
    const int tid = threadIdx.x;
    const int lr = tid >> 2;
    const int lk = (tid & 3) * 4;
    const float* xp = x + (size_t)(m0 + lr) * HDIM;
    const float* g1p = sg + (size_t)(n0 + lr) * HDIM;
    const float* g3p = su + (size_t)(n0 + lr) * HDIM;
    const int tx = tid & 15, ty = tid >> 4;
    float accG[4][4] = {{0}}, accU[4][4] = {{0}};

    for (int k0 = 0; k0 < HDIM; k0 += BK) {
        float4 av = *(const float4*)(xp + k0 + lk);
        As[lk + 0][lr] = av.x; As[lk + 1][lr] = av.y;
        As[lk + 2][lr] = av.z; As[lk + 3][lr] = av.w;
        float4 b1 = *(const float4*)(g1p + k0 + lk);
        B1s[lk + 0][lr] = b1.x; B1s[lk + 1][lr] = b1.y;
        B1s[lk + 2][lr] = b1.z; B1s[lk + 3][lr] = b1.w;
        float4 b3 = *(const float4*)(g3p + k0 + lk);
        B3s[lk + 0][lr] = b3.x; B3s[lk + 1][lr] = b3.y;
        B3s[lk + 2][lr] = b3.z; B3s[lk + 3][lr] = b3.w;
        __syncthreads();
        #pragma unroll
        for (int kk = 0; kk < BK; kk++) {
            float4 a  = *(const float4*)&As[kk][ty * 4];
            float4 b1v = *(const float4*)&B1s[kk][tx * 4];
            float4 b3v = *(const float4*)&B3s[kk][tx * 4];
            float aa[4] = {a.x, a.y, a.z, a.w};
            float g4[4] = {b1v.x, b1v.y, b1v.z, b1v.w};
            float u4[4] = {b3v.x, b3v.y, b3v.z, b3v.w};
            #pragma unroll
            for (int i = 0; i < 4; i++)
                #pragma unroll
                for (int j = 0; j < 4; j++) {
                    accG[i][j] = fmaf(aa[i], g4[j], accG[i][j]);
                    accU[i][j] = fmaf(aa[i], u4[j], accU[i][j]);
                }
        }
        __syncthreads();
    }
    #pragma unroll
    for (int i = 0; i < 4; i++) {
        int m = m0 + ty * 4 + i;
        float4 hv;
        float* o = (float*)&hv;
        #pragma unroll
        for (int j = 0; j < 4; j++) {
            float g = accG[i][j], u = accU[i][j];
            o[j] = g / (1.f + expf(-g)) * u;
        }
        *(float4*)(g_hs + (size_t)m * F2DIM + n0 + tx * 4) = hv;
    }
}

// Shared expert GEMM2: out[t,h] = sum_f g_hs[t,f]*sd[h,f]  (full overwrite of out)
__global__ __launch_bounds__(256) void shared_gemm2(const float* __restrict__ sd,
                                                    float* __restrict__ out) {
    const int m0 = blockIdx.y * BM;
    const int n0 = blockIdx.x * BN;
    __shared__ float As[BK][BM];
    __shared__ float Bs[BK][BN];
    const int tid = threadIdx.x;
    const int lr = tid >> 2;
    const int lk = (tid & 3) * 4;
    const float* ap = g_hs + (size_t)(m0 + lr) * F2DIM;
    const float* bp = sd + (size_t)(n0 + lr) * F2DIM;
    const int tx = tid & 15, ty = tid >> 4;
    float acc[4][4] = {{0}};

    for (int k0 = 0; k0 < F2DIM; k0 += BK) {
        float4 av = *(const float4*)(ap + k0 + lk);
        As[lk + 0][lr] = av.x; As[lk + 1][lr] = av.y;
        As[lk + 2][lr] = av.z; As[lk + 3][lr] = av.w;
        float4 bv = *(const float4*)(bp + k0 + lk);
        Bs[lk + 0][lr] = bv.x; Bs[lk + 1][lr] = bv.y;
        Bs[lk + 2][lr] = bv.z; Bs[lk + 3][lr] = bv.w;
        __syncthreads();
        #pragma unroll
        for (int kk = 0; kk < BK; kk++) {
            float4 a = *(const float4*)&As[kk][ty * 4];
            float4 b = *(const float4*)&Bs[kk][tx * 4];
            float aa[4] = {a.x, a.y, a.z, a.w};
            float bb[4] = {b.x, b.y, b.z, b.w};
            #pragma unroll
            for (int i = 0; i < 4; i++)
                #pragma unroll
                for (int j = 0; j < 4; j++)
                    acc[i][j] = fmaf(aa[i], bb[j], acc[i][j]);
        }
        __syncthreads();
    }
    #pragma unroll
    for (int i = 0; i < 4; i++) {
        int m = m0 + ty * 4 + i;
        *(float4*)(out + (size_t)m * HDIM + n0 + tx * 4) =
            make_float4(acc[i][0], acc[i][1], acc[i][2], acc[i][3]);
    }
}

// ---------------- launch ----------------
extern "C" void kernel_launch(void* const* d_in, const int* in_sizes, int n_in,
                              void* d_out, int out_size) {
    const float* x   = (const float*)d_in[0];   // [1,2048,1024]
    const float* gw  = (const float*)d_in[1];   // [64,1024]
    const float* eb  = (const float*)d_in[2];   // [64]
    const float* w1  = (const float*)d_in[3];   // [64,512,1024]
    const float* w2  = (const float*)d_in[4];   // [64,1024,512]
    const float* w3  = (const float*)d_in[5];   // [64,512,1024]
    const float* sg  = (const float*)d_in[6];   // [1024,1024]
    const float* su  = (const float*)d_in[7];   // [1024,1024]
    const float* sd  = (const float*)d_in[8];   // [1024,1024]
    float* out = (float*)d_out;                 // [1,2048,1024] fp32

    init_kernel<<<1, 64>>>();
    route_kernel<<<TOK, 256>>>(x, gw, eb);
    scan_kernel<<<1, 32>>>();
    assign_kernel<<<SKTOT / 256, 256>>>();

    // expert up-proj (gate/up fused, SwiGLU)
    expert_gemm1<<<dim3(FDIM / BN, CAPE / BM, NEXP), 256>>>(x, w1, w3);

    // shared expert (writes out fully), then expert down-proj atomically adds
    shared_gemm1<<<dim3(F2DIM / BN, TOK / BM), 256>>>(x, sg, su);
    shared_gemm2<<<dim3(HDIM / BN, TOK / BM), 256>>>(sd, out);

    expert_gemm2<<<dim3(HDIM / BN, CAPE / BM, NEXP), 256>>>(w2, out);
}

// round 2
// speedup vs baseline: 1.0888x; 1.0888x over previous
#include <cuda_runtime.h>
#include <cuda_bf16.h>
#include <math.h>

// ---------------- problem constants ----------------
#define TOK     2048
#define HDIM    1024
#define FDIM    512
#define F2DIM   1024
#define NEXP    64
#define TOPK    8
#define NGRP    8
#define TGRP    4
#define CAPE    1024
#define SKTOT   (TOK*TOPK)
#define SCALE   2.5f

typedef unsigned long long ull;

// ---------------- device scratch ----------------
__device__ float g_hbuf[SKTOT * FDIM];
__device__ float g_hs[TOK * F2DIM];
__device__ int   g_topk_idx[SKTOT];
__device__ float g_topk_w[SKTOT];
__device__ int   g_counts[NEXP];
__device__ int   g_fill[NEXP];
__device__ int   g_offsets[NEXP];
__device__ int   g_ecount[NEXP];
__device__ int   g_row_token[SKTOT];
__device__ float g_row_weight[SKTOT];

// ---------------- f32x2 packed helpers ----------------
__device__ __forceinline__ ull pk2(float lo, float hi) {
    ull r; asm("mov.b64 %0, {%1, %2};" : "=l"(r) : "f"(lo), "f"(hi)); return r;
}
__device__ __forceinline__ void fma2(ull& acc, ull a, ull b) {
    asm("fma.rn.f32x2 %0, %1, %2, %0;" : "+l"(acc) : "l"(a), "l"(b));
}
__device__ __forceinline__ float2 up2(ull v) {
    float2 r; asm("mov.b64 {%0, %1}, %2;" : "=f"(r.x), "=f"(r.y) : "l"(v)); return r;
}
__device__ __forceinline__ float silu_mul(float g, float u) {
    return g / (1.f + expf(-g)) * u;
}

// ---------------- init ----------------
__global__ void init_kernel() {
    int i = threadIdx.x;
    if (i < NEXP) { g_counts[i] = 0; g_fill[i] = 0; }
}

// ---------------- routing ----------------
__global__ __launch_bounds__(256) void route_kernel(const float* __restrict__ x,
                                                    const float* __restrict__ gw,
                                                    const float* __restrict__ eb) {
    const int t = blockIdx.x;
    __shared__ float xs[HDIM];
    __shared__ float sc[NEXP];
    __shared__ float sfc[NEXP];
    const int tid = threadIdx.x;
    const float* xr = x + (size_t)t * HDIM;
    #pragma unroll
    for (int i = 0; i < HDIM / 256; i++) xs[tid + i * 256] = xr[tid + i * 256];
    __syncthreads();

    const int warp = tid >> 5, lane = tid & 31;
    for (int q = 0; q < NEXP / 8; q++) {
        const int e = warp * 8 + q;
        const float* gwe = gw + (size_t)e * HDIM;
        float s = 0.f;
        #pragma unroll
        for (int i = 0; i < HDIM / 32; i++)
            s = fmaf(xs[i * 32 + lane], gwe[i * 32 + lane], s);
        #pragma unroll
        for (int off = 16; off; off >>= 1) s += __shfl_down_sync(0xffffffffu, s, off);
        if (lane == 0) {
            float sig = 1.f / (1.f + expf(-s));
            sc[e] = sig;
            sfc[e] = sig + eb[e];
        }
    }
    __syncthreads();

    if (tid == 0) {
        float gsc[NGRP];
        #pragma unroll
        for (int g = 0; g < NGRP; g++) {
            float m1 = -1e30f, m2 = -1e30f;
            #pragma unroll
            for (int j = 0; j < NEXP / NGRP; j++) {
                float v = sfc[g * (NEXP / NGRP) + j];
                if (v > m1) { m2 = m1; m1 = v; } else if (v > m2) { m2 = v; }
            }
            gsc[g] = m1 + m2;
        }
        bool gsel[NGRP];
        #pragma unroll
        for (int g = 0; g < NGRP; g++) gsel[g] = false;
        for (int it = 0; it < TGRP; it++) {
            float best = -1e30f; int bi = 0;
            #pragma unroll
            for (int g = 0; g < NGRP; g++)
                if (!gsel[g] && gsc[g] > best) { best = gsc[g]; bi = g; }
            gsel[bi] = true;
        }
        float tmp[NEXP];
        #pragma unroll
        for (int e = 0; e < NEXP; e++)
            tmp[e] = gsel[e / (NEXP / NGRP)] ? sfc[e] : 0.0f;
        int   idx[TOPK];
        float wv[TOPK];
        float wsum = 0.f;
        for (int k = 0; k < TOPK; k++) {
            float best = -1e30f; int bi = 0;
            #pragma unroll
            for (int e = 0; e < NEXP; e++)
                if (tmp[e] > best) { best = tmp[e]; bi = e; }
            idx[k] = bi; tmp[bi] = -1e30f;
            wv[k] = sc[bi]; wsum += wv[k];
        }
        float inv = SCALE / (wsum + 1e-20f);
        for (int k = 0; k < TOPK; k++) {
            g_topk_idx[t * TOPK + k] = idx[k];
            g_topk_w[t * TOPK + k] = wv[k] * inv;
            atomicAdd(&g_counts[idx[k]], 1);
        }
    }
}

__global__ void scan_kernel() {
    if (threadIdx.x == 0) {
        int run = 0;
        for (int e = 0; e < NEXP; e++) {
            int c = g_counts[e];
            int cc = c < CAPE ? c : CAPE;
            g_offsets[e] = run;
            g_ecount[e] = cc;
            run += cc;
        }
    }
}

__global__ void assign_kernel() {
    int s = blockIdx.x * blockDim.x + threadIdx.x;
    if (s >= SKTOT) return;
    int e = g_topk_idx[s];
    int p = atomicAdd(&g_fill[e], 1);
    if (p < CAPE) {
        int r = g_offsets[e] + p;
        g_row_token[r] = s / TOPK;
        g_row_weight[r] = g_topk_w[s];
    }
}

// =====================================================================
// GEMM1 (expert): 128x(64 dual)x16 tiles, f32x2 math, double buffered
// g_hbuf[r, n] = silu(x@w1^T) * (x@w3^T)
// =====================================================================
__global__ void __launch_bounds__(256, 2) expert_gemm1(const float* __restrict__ x,
                                                       const float* __restrict__ w1,
                                                       const float* __restrict__ w3) {
    const int e = blockIdx.z;
    const int me = g_ecount[e];
    const int m0 = blockIdx.y * 128;
    if (m0 >= me) return;
    const int n0 = blockIdx.x * 64;
    const int roff = g_offsets[e];

    __shared__ float As[2][16][128];
    __shared__ float B1s[2][16][64];
    __shared__ float B3s[2][16][64];
    __shared__ int tok[128];

    const int tid = threadIdx.x;
    if (tid < 128) {
        int m = m0 + tid;
        tok[tid] = (m < me) ? g_row_token[roff + m] : g_row_token[roff];
    }
    __syncthreads();

    const int al = tid >> 1, ak = (tid & 1) * 8;
    const int bl = tid >> 2, bk = (tid & 3) * 4;
    const float* ap  = x + (size_t)tok[al] * HDIM;
    const float* b1p = w1 + (size_t)e * FDIM * HDIM + (size_t)(n0 + bl) * HDIM;
    const float* b3p = w3 + (size_t)e * FDIM * HDIM + (size_t)(n0 + bl) * HDIM;

    auto load = [&](int buf, int k0) {
        float4 a0 = *(const float4*)(ap + k0 + ak);
        float4 a1 = *(const float4*)(ap + k0 + ak + 4);
        As[buf][ak + 0][al] = a0.x; As[buf][ak + 1][al] = a0.y;
        As[buf][ak + 2][al] = a0.z; As[buf][ak + 3][al] = a0.w;
        As[buf][ak + 4][al] = a1.x; As[buf][ak + 5][al] = a1.y;
        As[buf][ak + 6][al] = a1.z; As[buf][ak + 7][al] = a1.w;
        float4 b1 = *(const float4*)(b1p + k0 + bk);
        B1s[buf][bk + 0][bl] = b1.x; B1s[buf][bk + 1][bl] = b1.y;
        B1s[buf][bk + 2][bl] = b1.z; B1s[buf][bk + 3][bl] = b1.w;
        float4 b3 = *(const float4*)(b3p + k0 + bk);
        B3s[buf][bk + 0][bl] = b3.x; B3s[buf][bk + 1][bl] = b3.y;
        B3s[buf][bk + 2][bl] = b3.z; B3s[buf][bk + 3][bl] = b3.w;
    };

    const int tx = tid & 15, ty = tid >> 4;
    ull accG[8][2] = {}, accU[8][2] = {};

    load(0, 0);
    __syncthreads();
    int buf = 0;
    for (int k0 = 0; k0 < HDIM; k0 += 16) {
        if (k0 + 16 < HDIM) load(buf ^ 1, k0 + 16);
        #pragma unroll
        for (int kk = 0; kk < 16; kk++) {
            float a[8];
            *(float4*)&a[0] = *(const float4*)&As[buf][kk][ty * 8];
            *(float4*)&a[4] = *(const float4*)&As[buf][kk][ty * 8 + 4];
            ulonglong2 b1 = *(const ulonglong2*)&B1s[buf][kk][tx * 4];
            ulonglong2 b3 = *(const ulonglong2*)&B3s[buf][kk][tx * 4];
            #pragma unroll
            for (int i = 0; i < 8; i++) {
                ull aa = pk2(a[i], a[i]);
                fma2(accG[i][0], aa, b1.x); fma2(accG[i][1], aa, b1.y);
                fma2(accU[i][0], aa, b3.x); fma2(accU[i][1], aa, b3.y);
            }
        }
        __syncthreads();
        buf ^= 1;
    }

    #pragma unroll
    for (int i = 0; i < 8; i++) {
        int m = m0 + ty * 8 + i;
        if (m < me) {
            float2 g0 = up2(accG[i][0]), g1 = up2(accG[i][1]);
            float2 u0 = up2(accU[i][0]), u1 = up2(accU[i][1]);
            float4 hv;
            hv.x = silu_mul(g0.x, u0.x);
            hv.y = silu_mul(g0.y, u0.y);
            hv.z = silu_mul(g1.x, u1.x);
            hv.w = silu_mul(g1.y, u1.y);
            *(float4*)(g_hbuf + (size_t)(roff + m) * FDIM + n0 + tx * 4) = hv;
        }
    }
}

// =====================================================================
// GEMM2 (expert): 128x128x16, f32x2, fused weighted scatter-add
// =====================================================================
__global__ void __launch_bounds__(256, 2) expert_gemm2(const float* __restrict__ w2,
                                                       float* __restrict__ out) {
    const int e = blockIdx.z;
    const int me = g_ecount[e];
    const int m0 = blockIdx.y * 128;
    if (m0 >= me) return;
    const int n0 = blockIdx.x * 128;
    const int roff = g_offsets[e];

    __shared__ float As[2][16][128];
    __shared__ float Bs[2][16][128];
    __shared__ int tok[128];
    __shared__ float wrow[128];

    const int tid = threadIdx.x;
    if (tid < 128) {
        int m = m0 + tid;
        bool v = (m < me);
        tok[tid]  = v ? g_row_token[roff + m] : 0;
        wrow[tid] = v ? g_row_weight[roff + m] : 0.f;
    }

    const int al = tid >> 1, ak = (tid & 1) * 8;
    const int bl = tid >> 1, bk = (tid & 1) * 8;
    int mm = m0 + al;
    int arow = roff + ((mm < me) ? mm : 0);
    const float* ap = g_hbuf + (size_t)arow * FDIM;
    const float* bp = w2 + (size_t)e * HDIM * FDIM + (size_t)(n0 + bl) * FDIM;

    auto load = [&](int buf, int k0) {
        float4 a0 = *(const float4*)(ap + k0 + ak);
        float4 a1 = *(const float4*)(ap + k0 + ak + 4);
        As[buf][ak + 0][al] = a0.x; As[buf][ak + 1][al] = a0.y;
        As[buf][ak + 2][al] = a0.z; As[buf][ak + 3][al] = a0.w;
        As[buf][ak + 4][al] = a1.x; As[buf][ak + 5][al] = a1.y;
        As[buf][ak + 6][al] = a1.z; As[buf][ak + 7][al] = a1.w;
        float4 b0 = *(const float4*)(bp + k0 + bk);
        float4 b1 = *(const float4*)(bp + k0 + bk + 4);
        Bs[buf][bk + 0][bl] = b0.x; Bs[buf][bk + 1][bl] = b0.y;
        Bs[buf][bk + 2][bl] = b0.z; Bs[buf][bk + 3][bl] = b0.w;
        Bs[buf][bk + 4][bl] = b1.x; Bs[buf][bk + 5][bl] = b1.y;
        Bs[buf][bk + 6][bl] = b1.z; Bs[buf][bk + 7][bl] = b1.w;
    };

    const int tx = tid & 15, ty = tid >> 4;
    ull acc[8][4] = {};

    load(0, 0);
    __syncthreads();
    int buf = 0;
    for (int k0 = 0; k0 < FDIM; k0 += 16) {
        if (k0 + 16 < FDIM) load(buf ^ 1, k0 + 16);
        #pragma unroll
        for (int kk = 0; kk < 16; kk++) {
            float a[8];
            *(float4*)&a[0] = *(const float4*)&As[buf][kk][ty * 8];
            *(float4*)&a[4] = *(const float4*)&As[buf][kk][ty * 8 + 4];
            ulonglong2 b01 = *(const ulonglong2*)&Bs[buf][kk][tx * 8];
            ulonglong2 b23 = *(const ulonglong2*)&Bs[buf][kk][tx * 8 + 4];
            #pragma unroll
            for (int i = 0; i < 8; i++) {
                ull aa = pk2(a[i], a[i]);
                fma2(acc[i][0], aa, b01.x); fma2(acc[i][1], aa, b01.y);
                fma2(acc[i][2], aa, b23.x); fma2(acc[i][3], aa, b23.y);
            }
        }
        __syncthreads();
        buf ^= 1;
    }

    #pragma unroll
    for (int i = 0; i < 8; i++) {
        int m = m0 + ty * 8 + i;
        if (m < me) {
            int t = tok[ty * 8 + i];
            float w = wrow[ty * 8 + i];
            float* op = out + (size_t)t * HDIM + n0 + tx * 8;
            #pragma unroll
            for (int j = 0; j < 4; j++) {
                float2 v = up2(acc[i][j]);
                atomicAdd(op + 2 * j + 0, v.x * w);
                atomicAdd(op + 2 * j + 1, v.y * w);
            }
        }
    }
}

// =====================================================================
// Shared expert GEMM1: dense, 128x(64 dual)x16
// =====================================================================
__global__ void __launch_bounds__(256, 2) shared_gemm1(const float* __restrict__ x,
                                                       const float* __restrict__ sg,
                                                       const float* __restrict__ su) {
    const int m0 = blockIdx.y * 128;
    const int n0 = blockIdx.x * 64;

    __shared__ float As[2][16][128];
    __shared__ float B1s[2][16][64];
    __shared__ float B3s[2][16][64];

    const int tid = threadIdx.x;
    const int al = tid >> 1, ak = (tid & 1) * 8;
    const int bl = tid >> 2, bk = (tid & 3) * 4;
    const float* ap  = x + (size_t)(m0 + al) * HDIM;
    const float* b1p = sg + (size_t)(n0 + bl) * HDIM;
    const float* b3p = su + (size_t)(n0 + bl) * HDIM;

    auto load = [&](int buf, int k0) {
        float4 a0 = *(const float4*)(ap + k0 + ak);
        float4 a1 = *(const float4*)(ap + k0 + ak + 4);
        As[buf][ak + 0][al] = a0.x; As[buf][ak + 1][al] = a0.y;
        As[buf][ak + 2][al] = a0.z; As[buf][ak + 3][al] = a0.w;
        As[buf][ak + 4][al] = a1.x; As[buf][ak + 5][al] = a1.y;
        As[buf][ak + 6][al] = a1.z; As[buf][ak + 7][al] = a1.w;
        float4 b1 = *(const float4*)(b1p + k0 + bk);
        B1s[buf][bk + 0][bl] = b1.x; B1s[buf][bk + 1][bl] = b1.y;
        B1s[buf][bk + 2][bl] = b1.z; B1s[buf][bk + 3][bl] = b1.w;
        float4 b3 = *(const float4*)(b3p + k0 + bk);
        B3s[buf][bk + 0][bl] = b3.x; B3s[buf][bk + 1][bl] = b3.y;
        B3s[buf][bk + 2][bl] = b3.z; B3s[buf][bk + 3][bl] = b3.w;
    };

    const int tx = tid & 15, ty = tid >> 4;
    ull accG[8][2] = {}, accU[8][2] = {};

    load(0, 0);
    __syncthreads();
    int buf = 0;
    for (int k0 = 0; k0 < HDIM; k0 += 16) {
        if (k0 + 16 < HDIM) load(buf ^ 1, k0 + 16);
        #pragma unroll
        for (int kk = 0; kk < 16; kk++) {
            float a[8];
            *(float4*)&a[0] = *(const float4*)&As[buf][kk][ty * 8];
            *(float4*)&a[4] = *(const float4*)&As[buf][kk][ty * 8 + 4];
            ulonglong2 b1 = *(const ulonglong2*)&B1s[buf][kk][tx * 4];
            ulonglong2 b3 = *(const ulonglong2*)&B3s[buf][kk][tx * 4];
            #pragma unroll
            for (int i = 0; i < 8; i++) {
                ull aa = pk2(a[i], a[i]);
                fma2(accG[i][0], aa, b1.x); fma2(accG[i][1], aa, b1.y);
                fma2(accU[i][0], aa, b3.x); fma2(accU[i][1], aa, b3.y);
            }
        }
        __syncthreads();
        buf ^= 1;
    }

    #pragma unroll
    for (int i = 0; i < 8; i++) {
        int m = m0 + ty * 8 + i;
        float2 g0 = up2(accG[i][0]), g1 = up2(accG[i][1]);
        float2 u0 = up2(accU[i][0]), u1 = up2(accU[i][1]);
        float4 hv;
        hv.x = silu_mul(g0.x, u0.x);
        hv.y = silu_mul(g0.y, u0.y);
        hv.z = silu_mul(g1.x, u1.x);
        hv.w = silu_mul(g1.y, u1.y);
        *(float4*)(g_hs + (size_t)m * F2DIM + n0 + tx * 4) = hv;
    }
}

// =====================================================================
// Shared expert GEMM2: dense, 128x128x16, overwrites out
// =====================================================================
__global__ void __launch_bounds__(256, 2) shared_gemm2(const float* __restrict__ sd,
                                                       float* __restrict__ out) {
    const int m0 = blockIdx.y * 128;
    const int n0 = blockIdx.x * 128;

    __shared__ float As[2][16][128];
    __shared__ float Bs[2][16][128];

    const int tid = threadIdx.x;
    const int al = tid >> 1, ak = (tid & 1) * 8;
    const int bl = tid >> 1, bk = (tid & 1) * 8;
    const float* ap = g_hs + (size_t)(m0 + al) * F2DIM;
    const float* bp = sd + (size_t)(n0 + bl) * F2DIM;

    auto load = [&](int buf, int k0) {
        float4 a0 = *(const float4*)(ap + k0 + ak);
        float4 a1 = *(const float4*)(ap + k0 + ak + 4);
        As[buf][ak + 0][al] = a0.x; As[buf][ak + 1][al] = a0.y;
        As[buf][ak + 2][al] = a0.z; As[buf][ak + 3][al] = a0.w;
        As[buf][ak + 4][al] = a1.x; As[buf][ak + 5][al] = a1.y;
        As[buf][ak + 6][al] = a1.z; As[buf][ak + 7][al] = a1.w;
        float4 b0 = *(const float4*)(bp + k0 + bk);
        float4 b1 = *(const float4*)(bp + k0 + bk + 4);
        Bs[buf][bk + 0][bl] = b0.x; Bs[buf][bk + 1][bl] = b0.y;
        Bs[buf][bk + 2][bl] = b0.z; Bs[buf][bk + 3][bl] = b0.w;
        Bs[buf][bk + 4][bl] = b1.x; Bs[buf][bk + 5][bl] = b1.y;
        Bs[buf][bk + 6][bl] = b1.z; Bs[buf][bk + 7][bl] = b1.w;
    };

    const int tx = tid & 15, ty = tid >> 4;
    ull acc[8][4] = {};

    load(0, 0);
    __syncthreads();
    int buf = 0;
    for (int k0 = 0; k0 < F2DIM; k0 += 16) {
        if (k0 + 16 < F2DIM) load(buf ^ 1, k0 + 16);
        #pragma unroll
        for (int kk = 0; kk < 16; kk++) {
            float a[8];
            *(float4*)&a[0] = *(const float4*)&As[buf][kk][ty * 8];
            *(float4*)&a[4] = *(const float4*)&As[buf][kk][ty * 8 + 4];
            ulonglong2 b01 = *(const ulonglong2*)&Bs[buf][kk][tx * 8];
            ulonglong2 b23 = *(const ulonglong2*)&Bs[buf][kk][tx * 8 + 4];
            #pragma unroll
            for (int i = 0; i < 8; i++) {
                ull aa = pk2(a[i], a[i]);
                fma2(acc[i][0], aa, b01.x); fma2(acc[i][1], aa, b01.y);
                fma2(acc[i][2], aa, b23.x); fma2(acc[i][3], aa, b23.y);
            }
        }
        __syncthreads();
        buf ^= 1;
    }

    #pragma unroll
    for (int i = 0; i < 8; i++) {
        int m = m0 + ty * 8 + i;
        float* op = out + (size_t)m * HDIM + n0 + tx * 8;
        float2 v0 = up2(acc[i][0]), v1 = up2(acc[i][1]);
        float2 v2 = up2(acc[i][2]), v3 = up2(acc[i][3]);
        *(float4*)(op)     = make_float4(v0.x, v0.y, v1.x, v1.y);
        *(float4*)(op + 4) = make_float4(v2.x, v2.y, v3.x, v3.y);
    }
}

// ---------------- launch ----------------
extern "C" void kernel_launch(void* const* d_in, const int* in_sizes, int n_in,
                              void* d_out, int out_size) {
    const float* x   = (const float*)d_in[0];
    const float* gw  = (const float*)d_in[1];
    const float* eb  = (const float*)d_in[2];
    const float* w1  = (const float*)d_in[3];
    const float* w2  = (const float*)d_in[4];
    const float* w3  = (const float*)d_in[5];
    const float* sg  = (const float*)d_in[6];
    const float* su  = (const float*)d_in[7];
    const float* sd  = (const float*)d_in[8];
    float* out = (float*)d_out;

    init_kernel<<<1, 64>>>();
    route_kernel<<<TOK, 256>>>(x, gw, eb);
    scan_kernel<<<1, 32>>>();
    assign_kernel<<<SKTOT / 256, 256>>>();

    // expert up-proj (fused SwiGLU)
    expert_gemm1<<<dim3(FDIM / 64, CAPE / 128, NEXP), 256>>>(x, w1, w3);

    // shared expert: gemm1 then gemm2 (overwrites out)
    shared_gemm1<<<dim3(F2DIM / 64, TOK / 128), 256>>>(x, sg, su);
    shared_gemm2<<<dim3(HDIM / 128, TOK / 128), 256>>>(sd, out);

    // expert down-proj + weighted scatter-add (atomics into out)
    expert_gemm2<<<dim3(HDIM / 128, CAPE / 128, NEXP), 256>>>(w2, out);
}

// round 4
// speedup vs baseline: 2.2477x; 2.0644x over previous
#include <cuda_runtime.h>
#include <cuda_bf16.h>
#include <math.h>
#include <stdint.h>

// ---------------- problem constants ----------------
#define TOK     2048
#define HDIM    1024
#define FDIM    512
#define F2DIM   1024
#define NEXP    64
#define TOPK    8
#define NGRP    8
#define TGRP    4
#define CAPE    1024
#define SKTOT   (TOK*TOPK)
#define SCALE   2.5f

// ---------------- device scratch ----------------
__device__ __nv_bfloat16 g_hbuf_hi[SKTOT * FDIM];
__device__ __nv_bfloat16 g_hbuf_lo[SKTOT * FDIM];
__device__ __nv_bfloat16 g_hs_hi[TOK * F2DIM];
__device__ __nv_bfloat16 g_hs_lo[TOK * F2DIM];
__device__ int   g_topk_idx[SKTOT];
__device__ float g_topk_w[SKTOT];
__device__ int   g_counts[NEXP];
__device__ int   g_fill[NEXP];
__device__ int   g_offsets[NEXP];
__device__ int   g_ecount[NEXP];
__device__ int   g_row_token[SKTOT];
__device__ float g_row_weight[SKTOT];

// ---------------- helpers ----------------
__device__ __forceinline__ float silu_mul(float g, float u) {
    return g / (1.f + expf(-g)) * u;
}
__device__ __forceinline__ uint32_t smem_u32(const void* p) {
    uint32_t a;
    asm("{ .reg .u64 t; cvta.to.shared.u64 t, %1; cvt.u32.u64 %0, t; }" : "=r"(a) : "l"(p));
    return a;
}
// pack hi-bf16 (truncation) of two floats: low half = first element
__device__ __forceinline__ uint32_t hi_pair(float a, float b) {
    uint32_t r;
    asm("prmt.b32 %0, %1, %2, 0x7632;" : "=r"(r) : "r"(__float_as_uint(a)), "r"(__float_as_uint(b)));
    return r;
}
// pack rn-bf16 of residuals (a - hi(a)), (b - hi(b))
__device__ __forceinline__ uint32_t lo_pair(float a, float b) {
    float ra = a - __uint_as_float(__float_as_uint(a) & 0xFFFF0000u);
    float rb = b - __uint_as_float(__float_as_uint(b) & 0xFFFF0000u);
    uint32_t r;
    asm("cvt.rn.bf16x2.f32 %0, %1, %2;" : "=r"(r) : "f"(rb), "f"(ra));
    return r;
}
__device__ __forceinline__ void store_h(__nv_bfloat16* ph, __nv_bfloat16* pl, float h) {
    uint32_t b = __float_as_uint(h);
    *(unsigned short*)ph = (unsigned short)(b >> 16);
    float lo = h - __uint_as_float(b & 0xFFFF0000u);
    *pl = __float2bfloat16(lo);
}

// ---------------- mma.sync / ldmatrix primitives (base ISA) ----------------
__device__ __forceinline__ void ldsm4(uint32_t* r, uint32_t a) {
    asm volatile("ldmatrix.sync.aligned.m8n8.x4.shared.b16 {%0,%1,%2,%3}, [%4];"
                 : "=r"(r[0]), "=r"(r[1]), "=r"(r[2]), "=r"(r[3]) : "r"(a));
}
__device__ __forceinline__ void ldsm2(uint32_t* r, uint32_t a) {
    asm volatile("ldmatrix.sync.aligned.m8n8.x2.shared.b16 {%0,%1}, [%2];"
                 : "=r"(r[0]), "=r"(r[1]) : "r"(a));
}
__device__ __forceinline__ void mma_bf16(float* d, const uint32_t* a, const uint32_t* b) {
    asm volatile("mma.sync.aligned.m16n8k16.row.col.f32.bf16.bf16.f32 "
                 "{%0,%1,%2,%3}, {%4,%5,%6,%7}, {%8,%9}, {%0,%1,%2,%3};"
                 : "+f"(d[0]), "+f"(d[1]), "+f"(d[2]), "+f"(d[3])
                 : "r"(a[0]), "r"(a[1]), "r"(a[2]), "r"(a[3]), "r"(b[0]), "r"(b[1]));
}

// ---------------- SMEM tile layout ----------------
// planes: 0=AH 1=AL 2=BH 3=BL ; each 128 rows x 32 bf16, row stride 80B (pad)
#define STRIDE   80
#define PLANE    10240          // 128*80
#define SM_TILES 1024           // after toks/wro arrays
#define SMEM_SZ  (SM_TILES + 8 * PLANE)   // 82944 bytes

__device__ __forceinline__ uint32_t toff(int buf, int p) {
    return SM_TILES + (uint32_t)(buf * 4 + p) * PLANE;
}

// per-warp math on one K=32 chunk: acc += Ah*Bh + Ah*Bl + Al*Bh
__device__ __forceinline__ void mma_tile(float (&acc)[4][4][4], uint32_t smb, int buf,
                                         int wm, int wn, int lane) {
    const uint32_t base = smb + SM_TILES + (uint32_t)buf * 4 * PLANE;
    const uint32_t la = base + (uint32_t)((wm * 64 + (lane & 15)) * STRIDE) + (uint32_t)((lane >> 4) << 4);
    const uint32_t lb = base + 2 * PLANE + (uint32_t)((wn * 32 + (lane & 7)) * STRIDE)
                        + (uint32_t)(((lane >> 3) & 1) << 4);
#pragma unroll
    for (int ks = 0; ks < 2; ks++) {
        uint32_t af[4][4], bh[4][2], bl[4][2];
#pragma unroll
        for (int mi = 0; mi < 4; mi++) ldsm4(af[mi], la + mi * 16 * STRIDE + ks * 32);
#pragma unroll
        for (int ni = 0; ni < 4; ni++) {
            ldsm2(bh[ni], lb + ni * 8 * STRIDE + ks * 32);
            ldsm2(bl[ni], lb + PLANE + ni * 8 * STRIDE + ks * 32);
        }
#pragma unroll
        for (int mi = 0; mi < 4; mi++)
#pragma unroll
            for (int ni = 0; ni < 4; ni++) {
                mma_bf16(acc[mi][ni], af[mi], bh[ni]);
                mma_bf16(acc[mi][ni], af[mi], bl[ni]);
            }
#pragma unroll
        for (int mi = 0; mi < 4; mi++) ldsm4(af[mi], la + PLANE + mi * 16 * STRIDE + ks * 32);
#pragma unroll
        for (int mi = 0; mi < 4; mi++)
#pragma unroll
            for (int ni = 0; ni < 4; ni++) mma_bf16(acc[mi][ni], af[mi], bh[ni]);
    }
}

// ---------------- loaders ----------------
__device__ __forceinline__ void ldg16f(float* r, const float* __restrict__ p) {
#pragma unroll
    for (int i = 0; i < 4; i++) *(float4*)(r + i * 4) = *(const float4*)(p + i * 4);
}
__device__ __forceinline__ void sts_split16(char* ph, char* pl, const float* v) {
    uint4 H0, H1, L0, L1;
    H0.x = hi_pair(v[0], v[1]);   H0.y = hi_pair(v[2], v[3]);
    H0.z = hi_pair(v[4], v[5]);   H0.w = hi_pair(v[6], v[7]);
    H1.x = hi_pair(v[8], v[9]);   H1.y = hi_pair(v[10], v[11]);
    H1.z = hi_pair(v[12], v[13]); H1.w = hi_pair(v[14], v[15]);
    L0.x = lo_pair(v[0], v[1]);   L0.y = lo_pair(v[2], v[3]);
    L0.z = lo_pair(v[4], v[5]);   L0.w = lo_pair(v[6], v[7]);
    L1.x = lo_pair(v[8], v[9]);   L1.y = lo_pair(v[10], v[11]);
    L1.z = lo_pair(v[12], v[13]); L1.w = lo_pair(v[14], v[15]);
    *(uint4*)ph = H0; *(uint4*)(ph + 16) = H1;
    *(uint4*)pl = L0; *(uint4*)(pl + 16) = L1;
}

// ---------------- init ----------------
__global__ void init_kernel() {
    int i = threadIdx.x;
    if (i < NEXP) { g_counts[i] = 0; g_fill[i] = 0; }
}

// ---------------- routing ----------------
__global__ __launch_bounds__(256) void route_kernel(const float* __restrict__ x,
                                                    const float* __restrict__ gw,
                                                    const float* __restrict__ eb) {
    const int t = blockIdx.x;
    __shared__ float xs[HDIM];
    __shared__ float sc[NEXP];
    __shared__ float sfc[NEXP];
    const int tid = threadIdx.x;
    const float* xr = x + (size_t)t * HDIM;
    #pragma unroll
    for (int i = 0; i < HDIM / 256; i++) xs[tid + i * 256] = xr[tid + i * 256];
    __syncthreads();

    const int warp = tid >> 5, lane = tid & 31;
    for (int q = 0; q < NEXP / 8; q++) {
        const int e = warp * 8 + q;
        const float* gwe = gw + (size_t)e * HDIM;
        float s = 0.f;
        #pragma unroll
        for (int i = 0; i < HDIM / 32; i++)
            s = fmaf(xs[i * 32 + lane], gwe[i * 32 + lane], s);
        #pragma unroll
        for (int off = 16; off; off >>= 1) s += __shfl_down_sync(0xffffffffu, s, off);
        if (lane == 0) {
            float sig = 1.f / (1.f + expf(-s));
            sc[e] = sig;
            sfc[e] = sig + eb[e];
        }
    }
    __syncthreads();

    if (tid == 0) {
        float gsc[NGRP];
        #pragma unroll
        for (int g = 0; g < NGRP; g++) {
            float m1 = -1e30f, m2 = -1e30f;
            #pragma unroll
            for (int j = 0; j < NEXP / NGRP; j++) {
                float v = sfc[g * (NEXP / NGRP) + j];
                if (v > m1) { m2 = m1; m1 = v; } else if (v > m2) { m2 = v; }
            }
            gsc[g] = m1 + m2;
        }
        bool gsel[NGRP];
        #pragma unroll
        for (int g = 0; g < NGRP; g++) gsel[g] = false;
        for (int it = 0; it < TGRP; it++) {
            float best = -1e30f; int bi = 0;
            #pragma unroll
            for (int g = 0; g < NGRP; g++)
                if (!gsel[g] && gsc[g] > best) { best = gsc[g]; bi = g; }
            gsel[bi] = true;
        }
        float tmp[NEXP];
        #pragma unroll
        for (int e = 0; e < NEXP; e++)
            tmp[e] = gsel[e / (NEXP / NGRP)] ? sfc[e] : 0.0f;
        int   idx[TOPK];
        float wv[TOPK];
        float wsum = 0.f;
        for (int k = 0; k < TOPK; k++) {
            float best = -1e30f; int bi = 0;
            #pragma unroll
            for (int e = 0; e < NEXP; e++)
                if (tmp[e] > best) { best = tmp[e]; bi = e; }
            idx[k] = bi; tmp[bi] = -1e30f;
            wv[k] = sc[bi]; wsum += wv[k];
        }
        float inv = SCALE / (wsum + 1e-20f);
        for (int k = 0; k < TOPK; k++) {
            g_topk_idx[t * TOPK + k] = idx[k];
            g_topk_w[t * TOPK + k] = wv[k] * inv;
            atomicAdd(&g_counts[idx[k]], 1);
        }
    }
}

__global__ void scan_kernel() {
    if (threadIdx.x == 0) {
        int run = 0;
        for (int e = 0; e < NEXP; e++) {
            int c = g_counts[e];
            int cc = c < CAPE ? c : CAPE;
            g_offsets[e] = run;
            g_ecount[e] = cc;
            run += cc;
        }
    }
}

__global__ void assign_kernel() {
    int s = blockIdx.x * blockDim.x + threadIdx.x;
    if (s >= SKTOT) return;
    int e = g_topk_idx[s];
    int p = atomicAdd(&g_fill[e], 1);
    if (p < CAPE) {
        int r = g_offsets[e] + p;
        g_row_token[r] = s / TOPK;
        g_row_weight[r] = g_topk_w[s];
    }
}

// =====================================================================
// Expert GEMM1: gathered x [me,1024] @ interleaved(w1,w3) -> SwiGLU -> hbuf
// block: 128 rows x 64 logical F cols (128 interleaved B rows)
// =====================================================================
__global__ void __launch_bounds__(256) eg1_kernel(const float* __restrict__ x,
                                                  const float* __restrict__ w1,
                                                  const float* __restrict__ w3) {
    extern __shared__ char sm[];
    const int tid = threadIdx.x, lane = tid & 31, wid = tid >> 5;
    const int wm = wid & 1, wn = wid >> 1;
    const int e  = blockIdx.z;
    const int me = g_ecount[e];
    const int m0 = blockIdx.y * 128;
    if (m0 >= me) return;
    const int f0 = blockIdx.x * 64;
    const int roff = g_offsets[e];
    const uint32_t smb = smem_u32(sm);

    int* toks = (int*)sm;
    if (tid < 128) {
        int m = m0 + tid;
        toks[tid] = g_row_token[roff + ((m < me) ? m : 0)];
    }
    __syncthreads();

    const int lr = tid >> 1, kseg = (tid & 1) * 16;
    const float* apf = x + (size_t)toks[lr] * HDIM + kseg;
    const int nb = lr;
    const float* bpf = ((nb & 1) ? w3 : w1) + ((size_t)e * FDIM + f0 + (nb >> 1)) * HDIM + kseg;
    const uint32_t soff = (uint32_t)(lr * STRIDE + kseg * 2);

    float ra[16], rb[16];
    ldg16f(ra, apf); ldg16f(rb, bpf);
    sts_split16(sm + toff(0, 0) + soff, sm + toff(0, 1) + soff, ra);
    sts_split16(sm + toff(0, 2) + soff, sm + toff(0, 3) + soff, rb);
    __syncthreads();

    float acc[4][4][4];
#pragma unroll
    for (int i = 0; i < 4; i++)
#pragma unroll
        for (int j = 0; j < 4; j++)
#pragma unroll
            for (int k = 0; k < 4; k++) acc[i][j][k] = 0.f;

    int buf = 0;
    const int NCH = HDIM / 32;
    for (int ch = 0; ch < NCH; ch++) {
        if (ch + 1 < NCH) { ldg16f(ra, apf + (ch + 1) * 32); ldg16f(rb, bpf + (ch + 1) * 32); }
        mma_tile(acc, smb, buf, wm, wn, lane);
        if (ch + 1 < NCH) {
            sts_split16(sm + toff(buf ^ 1, 0) + soff, sm + toff(buf ^ 1, 1) + soff, ra);
            sts_split16(sm + toff(buf ^ 1, 2) + soff, sm + toff(buf ^ 1, 3) + soff, rb);
        }
        __syncthreads();
        buf ^= 1;
    }

    // epilogue: (d0,d1) = (gate, up) for one logical col; (d2,d3) row+8
#pragma unroll
    for (int mi = 0; mi < 4; mi++) {
        int r = m0 + wm * 64 + mi * 16 + (lane >> 2);
#pragma unroll
        for (int ni = 0; ni < 4; ni++) {
            int lc = f0 + wn * 16 + ni * 4 + (lane & 3);
            float* d = acc[mi][ni];
            if (r < me) {
                float h = silu_mul(d[0], d[1]);
                size_t o = (size_t)(roff + r) * FDIM + lc;
                store_h(g_hbuf_hi + o, g_hbuf_lo + o, h);
            }
            if (r + 8 < me) {
                float h = silu_mul(d[2], d[3]);
                size_t o = (size_t)(roff + r + 8) * FDIM + lc;
                store_h(g_hbuf_hi + o, g_hbuf_lo + o, h);
            }
        }
    }
}

// =====================================================================
// Expert GEMM2: hbuf planes [me,512] @ w2 -> weighted atomicAdd into out
// block: 128 rows x 128 HDIM cols
// =====================================================================
__global__ void __launch_bounds__(256) eg2_kernel(const float* __restrict__ w2,
                                                  float* __restrict__ out) {
    extern __shared__ char sm[];
    const int tid = threadIdx.x, lane = tid & 31, wid = tid >> 5;
    const int wm = wid & 1, wn = wid >> 1;
    const int e  = blockIdx.z;
    const int me = g_ecount[e];
    const int m0 = blockIdx.y * 128;
    if (m0 >= me) return;
    const int n0 = blockIdx.x * 128;
    const int roff = g_offsets[e];
    const uint32_t smb = smem_u32(sm);

    int*   toks = (int*)sm;
    float* wro  = (float*)(sm + 512);
    if (tid < 128) {
        int m = m0 + tid;
        bool v = m < me;
        toks[tid] = v ? g_row_token[roff + m] : 0;
        wro[tid]  = v ? g_row_weight[roff + m] : 0.f;
    }
    __syncthreads();

    const int lr = tid >> 1, kseg = (tid & 1) * 16;
    int mm = m0 + lr;
    size_t arow = (size_t)(roff + ((mm < me) ? mm : (me - 1)));
    const __nv_bfloat16* aph = g_hbuf_hi + arow * FDIM + kseg;
    const __nv_bfloat16* apl = g_hbuf_lo + arow * FDIM + kseg;
    const float* bpf = w2 + ((size_t)e * HDIM + n0 + lr) * FDIM + kseg;
    const uint32_t soff = (uint32_t)(lr * STRIDE + kseg * 2);

    uint4 rah[2], ral[2]; float rb[16];
    rah[0] = *(const uint4*)aph; rah[1] = *(const uint4*)(aph + 8);
    ral[0] = *(const uint4*)apl; ral[1] = *(const uint4*)(apl + 8);
    ldg16f(rb, bpf);
    *(uint4*)(sm + toff(0, 0) + soff) = rah[0]; *(uint4*)(sm + toff(0, 0) + soff + 16) = rah[1];
    *(uint4*)(sm + toff(0, 1) + soff) = ral[0]; *(uint4*)(sm + toff(0, 1) + soff + 16) = ral[1];
    sts_split16(sm + toff(0, 2) + soff, sm + toff(0, 3) + soff, rb);
    __syncthreads();

    float acc[4][4][4];
#pragma unroll
    for (int i = 0; i < 4; i++)
#pragma unroll
        for (int j = 0; j < 4; j++)
#pragma unroll
            for (int k = 0; k < 4; k++) acc[i][j][k] = 0.f;

    int buf = 0;
    const int NCH = FDIM / 32;
    for (int ch = 0; ch < NCH; ch++) {
        if (ch + 1 < NCH) {
            const __nv_bfloat16* ph = aph + (ch + 1) * 32;
            const __nv_bfloat16* pl = apl + (ch + 1) * 32;
            rah[0] = *(const uint4*)ph; rah[1] = *(const uint4*)(ph + 8);
            ral[0] = *(const uint4*)pl; ral[1] = *(const uint4*)(pl + 8);
            ldg16f(rb, bpf + (ch + 1) * 32);
        }
        mma_tile(acc, smb, buf, wm, wn, lane);
        if (ch + 1 < NCH) {
            *(uint4*)(sm + toff(buf ^ 1, 0) + soff) = rah[0];
            *(uint4*)(sm + toff(buf ^ 1, 0) + soff + 16) = rah[1];
            *(uint4*)(sm + toff(buf ^ 1, 1) + soff) = ral[0];
            *(uint4*)(sm + toff(buf ^ 1, 1) + soff + 16) = ral[1];
            sts_split16(sm + toff(buf ^ 1, 2) + soff, sm + toff(buf ^ 1, 3) + soff, rb);
        }
        __syncthreads();
        buf ^= 1;
    }

#pragma unroll
    for (int mi = 0; mi < 4; mi++) {
        int lrow = wm * 64 + mi * 16 + (lane >> 2);
        int r = m0 + lrow;
        int t0 = toks[lrow], t1 = toks[lrow + 8];
        float w0 = wro[lrow], w1v = wro[lrow + 8];
#pragma unroll
        for (int ni = 0; ni < 4; ni++) {
            int col = n0 + wn * 32 + ni * 8 + 2 * (lane & 3);
            float* d = acc[mi][ni];
            if (r < me) {
                atomicAdd(out + (size_t)t0 * HDIM + col,     d[0] * w0);
                atomicAdd(out + (size_t)t0 * HDIM + col + 1, d[1] * w0);
            }
            if (r + 8 < me) {
                atomicAdd(out + (size_t)t1 * HDIM + col,     d[2] * w1v);
                atomicAdd(out + (size_t)t1 * HDIM + col + 1, d[3] * w1v);
            }
        }
    }
}

// =====================================================================
// Shared GEMM1: x [2048,1024] @ interleaved(sg,su) -> SwiGLU -> hs planes
// =====================================================================
__global__ void __launch_bounds__(256) sg1_kernel(const float* __restrict__ x,
                                                  const float* __restrict__ sg,
                                                  const float* __restrict__ su) {
    extern __shared__ char sm[];
    const int tid = threadIdx.x, lane = tid & 31, wid = tid >> 5;
    const int wm = wid & 1, wn = wid >> 1;
    const int m0 = blockIdx.y * 128;
    const int f0 = blockIdx.x * 64;
    const uint32_t smb = smem_u32(sm);

    const int lr = tid >> 1, kseg = (tid & 1) * 16;
    const float* apf = x + (size_t)(m0 + lr) * HDIM + kseg;
    const int nb = lr;
    const float* bpf = ((nb & 1) ? su : sg) + (size_t)(f0 + (nb >> 1)) * HDIM + kseg;
    const uint32_t soff = (uint32_t)(lr * STRIDE + kseg * 2);

    float ra[16], rb[16];
    ldg16f(ra, apf); ldg16f(rb, bpf);
    sts_split16(sm + toff(0, 0) + soff, sm + toff(0, 1) + soff, ra);
    sts_split16(sm + toff(0, 2) + soff, sm + toff(0, 3) + soff, rb);
    __syncthreads();

    float acc[4][4][4];
#pragma unroll
    for (int i = 0; i < 4; i++)
#pragma unroll
        for (int j = 0; j < 4; j++)
#pragma unroll
            for (int k = 0; k < 4; k++) acc[i][j][k] = 0.f;

    int buf = 0;
    const int NCH = HDIM / 32;
    for (int ch = 0; ch < NCH; ch++) {
        if (ch + 1 < NCH) { ldg16f(ra, apf + (ch + 1) * 32); ldg16f(rb, bpf + (ch + 1) * 32); }
        mma_tile(acc, smb, buf, wm, wn, lane);
        if (ch + 1 < NCH) {
            sts_split16(sm + toff(buf ^ 1, 0) + soff, sm + toff(buf ^ 1, 1) + soff, ra);
            sts_split16(sm + toff(buf ^ 1, 2) + soff, sm + toff(buf ^ 1, 3) + soff, rb);
        }
        __syncthreads();
        buf ^= 1;
    }

#pragma unroll
    for (int mi = 0; mi < 4; mi++) {
        int r = m0 + wm * 64 + mi * 16 + (lane >> 2);
#pragma unroll
        for (int ni = 0; ni < 4; ni++) {
            int lc = f0 + wn * 16 + ni * 4 + (lane & 3);
            float* d = acc[mi][ni];
            float h0 = silu_mul(d[0], d[1]);
            float h1 = silu_mul(d[2], d[3]);
            size_t o0 = (size_t)r * F2DIM + lc;
            size_t o1 = (size_t)(r + 8) * F2DIM + lc;
            store_h(g_hs_hi + o0, g_hs_lo + o0, h0);
            store_h(g_hs_hi + o1, g_hs_lo + o1, h1);
        }
    }
}

// =====================================================================
// Shared GEMM2: hs planes [2048,1024] @ sd -> overwrite out
// =====================================================================
__global__ void __launch_bounds__(256) sg2_kernel(const float* __restrict__ sd,
                                                  float* __restrict__ out) {
    extern __shared__ char sm[];
    const int tid = threadIdx.x, lane = tid & 31, wid = tid >> 5;
    const int wm = wid & 1, wn = wid >> 1;
    const int m0 = blockIdx.y * 128;
    const int n0 = blockIdx.x * 128;
    const uint32_t smb = smem_u32(sm);

    const int lr = tid >> 1, kseg = (tid & 1) * 16;
    const __nv_bfloat16* aph = g_hs_hi + (size_t)(m0 + lr) * F2DIM + kseg;
    const __nv_bfloat16* apl = g_hs_lo + (size_t)(m0 + lr) * F2DIM + kseg;
    const float* bpf = sd + (size_t)(n0 + lr) * F2DIM + kseg;
    const uint32_t soff = (uint32_t)(lr * STRIDE + kseg * 2);

    uint4 rah[2], ral[2]; float rb[16];
    rah[0] = *(const uint4*)aph; rah[1] = *(const uint4*)(aph + 8);
    ral[0] = *(const uint4*)apl; ral[1] = *(const uint4*)(apl + 8);
    ldg16f(rb, bpf);
    *(uint4*)(sm + toff(0, 0) + soff) = rah[0]; *(uint4*)(sm + toff(0, 0) + soff + 16) = rah[1];
    *(uint4*)(sm + toff(0, 1) + soff) = ral[0]; *(uint4*)(sm + toff(0, 1) + soff + 16) = ral[1];
    sts_split16(sm + toff(0, 2) + soff, sm + toff(0, 3) + soff, rb);
    __syncthreads();

    float acc[4][4][4];
#pragma unroll
    for (int i = 0; i < 4; i++)
#pragma unroll
        for (int j = 0; j < 4; j++)
#pragma unroll
            for (int k = 0; k < 4; k++) acc[i][j][k] = 0.f;

    int buf = 0;
    const int NCH = F2DIM / 32;
    for (int ch = 0; ch < NCH; ch++) {
        if (ch + 1 < NCH) {
            const __nv_bfloat16* ph = aph + (ch + 1) * 32;
            const __nv_bfloat16* pl = apl + (ch + 1) * 32;
            rah[0] = *(const uint4*)ph; rah[1] = *(const uint4*)(ph + 8);
            ral[0] = *(const uint4*)pl; ral[1] = *(const uint4*)(pl + 8);
            ldg16f(rb, bpf + (ch + 1) * 32);
        }
        mma_tile(acc, smb, buf, wm, wn, lane);
        if (ch + 1 < NCH) {
            *(uint4*)(sm + toff(buf ^ 1, 0) + soff) = rah[0];
            *(uint4*)(sm + toff(buf ^ 1, 0) + soff + 16) = rah[1];
            *(uint4*)(sm + toff(buf ^ 1, 1) + soff) = ral[0];
            *(uint4*)(sm + toff(buf ^ 1, 1) + soff + 16) = ral[1];
            sts_split16(sm + toff(buf ^ 1, 2) + soff, sm + toff(buf ^ 1, 3) + soff, rb);
        }
        __syncthreads();
        buf ^= 1;
    }

#pragma unroll
    for (int mi = 0; mi < 4; mi++) {
        int r = m0 + wm * 64 + mi * 16 + (lane >> 2);
#pragma unroll
        for (int ni = 0; ni < 4; ni++) {
            int col = n0 + wn * 32 + ni * 8 + 2 * (lane & 3);
            float* d = acc[mi][ni];
            *(float2*)(out + (size_t)r * HDIM + col)       = make_float2(d[0], d[1]);
            *(float2*)(out + (size_t)(r + 8) * HDIM + col) = make_float2(d[2], d[3]);
        }
    }
}

// ---------------- launch ----------------
extern "C" void kernel_launch(void* const* d_in, const int* in_sizes, int n_in,
                              void* d_out, int out_size) {
    const float* x   = (const float*)d_in[0];
    const float* gw  = (const float*)d_in[1];
    const float* eb  = (const float*)d_in[2];
    const float* w1  = (const float*)d_in[3];
    const float* w2  = (const float*)d_in[4];
    const float* w3  = (const float*)d_in[5];
    const float* sg  = (const float*)d_in[6];
    const float* su  = (const float*)d_in[7];
    const float* sd  = (const float*)d_in[8];
    float* out = (float*)d_out;

    static bool attr_done = false;
    if (!attr_done) {
        cudaFuncSetAttribute(eg1_kernel, cudaFuncAttributeMaxDynamicSharedMemorySize, SMEM_SZ);
        cudaFuncSetAttribute(eg2_kernel, cudaFuncAttributeMaxDynamicSharedMemorySize, SMEM_SZ);
        cudaFuncSetAttribute(sg1_kernel, cudaFuncAttributeMaxDynamicSharedMemorySize, SMEM_SZ);
        cudaFuncSetAttribute(sg2_kernel, cudaFuncAttributeMaxDynamicSharedMemorySize, SMEM_SZ);
        attr_done = true;
    }

    init_kernel<<<1, 64>>>();
    route_kernel<<<TOK, 256>>>(x, gw, eb);
    scan_kernel<<<1, 32>>>();
    assign_kernel<<<SKTOT / 256, 256>>>();

    // expert up-proj + SwiGLU -> hbuf bf16 hi/lo planes
    eg1_kernel<<<dim3(FDIM / 64, CAPE / 128, NEXP), 256, SMEM_SZ>>>(x, w1, w3);

    // shared expert: sg1 -> hs planes, sg2 overwrites out
    sg1_kernel<<<dim3(F2DIM / 64, TOK / 128), 256, SMEM_SZ>>>(x, sg, su);
    sg2_kernel<<<dim3(HDIM / 128, TOK / 128), 256, SMEM_SZ>>>(sd, out);

    // expert down-proj + weighted scatter-add
    eg2_kernel<<<dim3(HDIM / 128, CAPE / 128, NEXP), 256, SMEM_SZ>>>(w2, out);
}